// round 16
// baseline (speedup 1.0000x reference)
#include <cuda_runtime.h>

#define B_   16
#define C_   384
#define H_   56
#define W_   56
#define HW_  3136
#define NHW_ 50176
#define TOT_ 19267584
#define KL   31
#define PL   15
#define KS   5
#define TS   86        // 56 + 2*15
#define STR  90        // even stride, gcd(90,32)=2 -> conflict-free float2 rows
#define WIDE 14        // output columns per thread
#define NTHR 224       // 56 rows x 4 strips -- every lane works
#define TILE_PAD (TS * STR)   // 7740, multiple of 4

typedef unsigned long long ull;

// Scratch (allocation-free contract: __device__ globals)
__device__ float g_yl[TOT_];
__device__ float g_ys[TOT_];
__device__ float g_acc[C_ * 4];   // per channel: sumL, sqL, sumS, sqS
__device__ float g_prm[C_ * 3];   // per channel: aL, aS, bias

__device__ __forceinline__ ull fma2(ull a, ull b, ull c) {
    ull d; asm("fma.rn.f32x2 %0, %1, %2, %3;" : "=l"(d) : "l"(a), "l"(b), "l"(c)); return d;
}
__device__ __forceinline__ void unpack2(ull v, float& lo, float& hi) {
    asm("mov.b64 {%0, %1}, %2;" : "=f"(lo), "=f"(hi) : "l"(v));
}
__device__ __forceinline__ float lo2(ull v) { float l, h; unpack2(v, l, h); return l; }
__device__ __forceinline__ float hi2(ull v) { float l, h; unpack2(v, l, h); return h; }
__device__ __forceinline__ ull pack2(float lo, float hi) {
    ull r; asm("mov.b64 %0, {%1, %2};" : "=l"(r) : "f"(lo), "f"(hi)); return r;
}

__global__ void k_zero() {
    int i = blockIdx.x * blockDim.x + threadIdx.x;
    if (i < C_ * 4) g_acc[i] = 0.f;
}

// One 31-tap kernel row with parity-split f32x2 accumulation.
// Window: 8 aligned float2 pairs v[m&7] covering x[2m..2m+15], rolling.
// Even tap j: accA[p] += v[(j/2+p)&7]   * (w,w)   (accA[p] = (y[2p],   y[2p+1]))
// Odd  tap j: accB[p] += v[((j-1)/2+p)&7]*(w,w)   (accB[p] = (y[2p-1], y[2p]))
//             + scalar y13 part: x[j+13] = lo(v[((j-1)/2+7)&7])
// FUSE rows (i=13..17): scalar 5x5 taps j=13..17 read window components directly.
template<int FUSE>
__device__ __forceinline__ void conv_row_p(const float* __restrict__ xr,
                                           const ull* __restrict__ w2row,
                                           const float* __restrict__ wsrow,
                                           ull* __restrict__ accA,
                                           ull* __restrict__ accB,
                                           float& yO13,
                                           float* __restrict__ accS) {
    ull v[8];
    #pragma unroll
    for (int u = 0; u < 8; u++) v[u] = *(const ull*)&xr[2 * u];

    #pragma unroll
    for (int j = 0; j < KL; j++) {
        const ull wv = w2row[j];                 // LDS.64 broadcast (w,w)
        if ((j & 1) == 0) {
            const int mm = j >> 1;
            #pragma unroll
            for (int p = 0; p < 7; p++)
                accA[p] = fma2(v[(mm + p) & 7], wv, accA[p]);
        } else {
            const int mm = (j - 1) >> 1;
            #pragma unroll
            for (int p = 0; p < 7; p++)
                accB[p] = fma2(v[(mm + p) & 7], wv, accB[p]);
            yO13 = fmaf(lo2(v[(mm + 7) & 7]), lo2(wv), yO13);   // x[j+13]
        }
        if (FUSE && j >= 13 && j <= 17) {        // fused 5x5, same window operands
            const float sv = wsrow[j - 13];
            #pragma unroll
            for (int t = 0; t < WIDE; t++) {
                const int g = j + t;
                const ull pv = v[(g >> 1) & 7];
                const float xs = (g & 1) ? hi2(pv) : lo2(pv);
                accS[t] = fmaf(xs, sv, accS[t]);
            }
        }
        if ((j & 1) && j <= 27) {                // refill AFTER use (aligned pair)
            const int mm = (j - 1) >> 1;
            v[mm & 7] = *(const ull*)&xr[j + 15];
        }
    }
}

__global__ __launch_bounds__(NTHR, 4) void k_conv(const float* __restrict__ x,
                                                  const float* __restrict__ wl_g,
                                                  const float* __restrict__ ws_g) {
    __shared__ __align__(16) float tile[TILE_PAD];
    __shared__ __align__(16) ull  wl2[KL * 32];    // packed (w,w) rows, padded
    __shared__ float ws[32];
    __shared__ float red[7 * 4];

    const int blk = blockIdx.x;          // n*C + c
    const int c   = blk % C_;
    const int tid = threadIdx.x;
    const float* img = x + (size_t)blk * HW_;

    const int row   = tid % 56;          // output row / interior row
    const int strip = tid / 56;          // 0..3
    const int col0  = strip * WIDE;      // 0, 14, 28, 42 (all even)

    // ---- phase 1: zero full padded tile (float4), load packed weights ----
    #pragma unroll
    for (int u = 0; u < TILE_PAD / 4; u += NTHR) {
        int idx = u + tid;
        if (idx < TILE_PAD / 4) ((float4*)tile)[idx] = make_float4(0.f, 0.f, 0.f, 0.f);
    }
    for (int idx = tid; idx < KL * 32; idx += NTHR) {
        int i = idx >> 5, j = idx & 31;
        float w = (j < KL) ? wl_g[c * KL * KL + i * KL + j] : 0.f;
        wl2[idx] = pack2(w, w);
    }
    if (tid < KS * KS) ws[tid] = ws_g[c * KS * KS + tid];
    __syncthreads();

    // ---- phase 2: interior load, exact fit: thread = (row, 14-col strip) ----
    {
        const float* src = img + row * W_ + col0;   // even offset -> 8B aligned
        float* dst = &tile[(row + PL) * STR + PL + col0];
        #pragma unroll
        for (int t = 0; t < WIDE; t += 2) {
            float2 v = *(const float2*)&src[t];
            dst[t]     = v.x;
            dst[t + 1] = v.y;
        }
    }
    __syncthreads();

    const size_t ob = (size_t)blk * HW_ + (size_t)row * W_ + col0;
    float sL = 0.f, qL = 0.f, sS = 0.f, qS = 0.f;

    // ---- fused 31x31 + 5x5 depthwise conv, f32x2 parity-split accumulation ----
    {
        ull accA[7], accB[7];
        #pragma unroll
        for (int p = 0; p < 7; p++) { accA[p] = 0ull; accB[p] = 0ull; }
        float yO13 = 0.f;

        #pragma unroll 1
        for (int i = 0; i < 13; i++)
            conv_row_p<0>(&tile[(row + i) * STR + col0], &wl2[i * 32], ws,
                          accA, accB, yO13, (float*)0);

        {
            float accS[WIDE];
            #pragma unroll
            for (int t = 0; t < WIDE; t++) accS[t] = 0.f;

            #pragma unroll 1
            for (int i = 13; i < 18; i++)
                conv_row_p<1>(&tile[(row + i) * STR + col0], &wl2[i * 32],
                              &ws[(i - 13) * KS], accA, accB, yO13, accS);

            #pragma unroll
            for (int t = 0; t < WIDE; t += 2)
                *(float2*)&g_ys[ob + t] = make_float2(accS[t], accS[t+1]);
            #pragma unroll
            for (int t = 0; t < WIDE; t++) {
                sS += accS[t]; qS = fmaf(accS[t], accS[t], qS);
            }
        }

        #pragma unroll 1
        for (int i = 18; i < KL; i++)
            conv_row_p<0>(&tile[(row + i) * STR + col0], &wl2[i * 32], ws,
                          accA, accB, yO13, (float*)0);

        // epilogue: combine parity halves
        float y[WIDE];
        #pragma unroll
        for (int p = 0; p < 7; p++)
            y[2 * p] = lo2(accA[p]) + hi2(accB[p]);
        #pragma unroll
        for (int p = 0; p < 6; p++)
            y[2 * p + 1] = hi2(accA[p]) + lo2(accB[p + 1]);
        y[13] = hi2(accA[6]) + yO13;

        #pragma unroll
        for (int t = 0; t < WIDE; t += 2)
            *(float2*)&g_yl[ob + t] = make_float2(y[t], y[t+1]);
        #pragma unroll
        for (int t = 0; t < WIDE; t++) {
            sL += y[t]; qL = fmaf(y[t], y[t], qL);
        }
    }

    // ---- block reduction of the 4 stats (7 warps) ----
    #pragma unroll
    for (int o = 16; o; o >>= 1) {
        sL += __shfl_down_sync(0xffffffffu, sL, o);
        qL += __shfl_down_sync(0xffffffffu, qL, o);
        sS += __shfl_down_sync(0xffffffffu, sS, o);
        qS += __shfl_down_sync(0xffffffffu, qS, o);
    }
    const int lane = tid & 31, wpid = tid >> 5;
    if (lane == 0) { red[wpid*4+0]=sL; red[wpid*4+1]=qL; red[wpid*4+2]=sS; red[wpid*4+3]=qS; }
    __syncthreads();
    if (tid < 4) {
        float v = 0.f;
        #pragma unroll
        for (int ww = 0; ww < 7; ww++) v += red[ww * 4 + tid];
        atomicAdd(&g_acc[c * 4 + tid], v);
    }
}

__global__ void k_stats(const float* __restrict__ gL, const float* __restrict__ bL,
                        const float* __restrict__ gS, const float* __restrict__ bS) {
    int c = blockIdx.x * blockDim.x + threadIdx.x;
    if (c >= C_) return;
    const float inv_n = 1.f / (float)NHW_;
    float mL = g_acc[c*4+0] * inv_n;
    float vL = g_acc[c*4+1] * inv_n - mL * mL;
    float aL = gL[c] * rsqrtf(vL + 1e-5f);
    float mS = g_acc[c*4+2] * inv_n;
    float vS = g_acc[c*4+3] * inv_n - mS * mS;
    float aS = gS[c] * rsqrtf(vS + 1e-5f);
    g_prm[c]        = aL;
    g_prm[C_ + c]   = aS;
    g_prm[2*C_ + c] = bL[c] - mL * aL + bS[c] - mS * aS;
}

__global__ __launch_bounds__(256) void k_out(float* __restrict__ out) {
    int i = blockIdx.x * blockDim.x + threadIdx.x;
    if (i >= TOT_ / 4) return;
    int e = i * 4;
    int c = (e / HW_) % C_;          // HW_ divisible by 4 -> channel constant in float4
    float aL = g_prm[c], aS = g_prm[C_ + c], bb = g_prm[2*C_ + c];
    float4 l = ((const float4*)g_yl)[i];
    float4 s = ((const float4*)g_ys)[i];
    float4 o;
    o.x = fmaf(aL, l.x, fmaf(aS, s.x, bb));
    o.y = fmaf(aL, l.y, fmaf(aS, s.y, bb));
    o.z = fmaf(aL, l.z, fmaf(aS, s.z, bb));
    o.w = fmaf(aL, l.w, fmaf(aS, s.w, bb));
    ((float4*)out)[i] = o;
}

extern "C" void kernel_launch(void* const* d_in, const int* in_sizes, int n_in,
                              void* d_out, int out_size) {
    const float* x  = (const float*)d_in[0];
    const float* wl = (const float*)d_in[1];
    const float* gl = (const float*)d_in[2];
    const float* bl = (const float*)d_in[3];
    const float* ws = (const float*)d_in[4];
    const float* gs = (const float*)d_in[5];
    const float* bs = (const float*)d_in[6];

    k_zero<<<6, 256>>>();
    k_conv<<<B_ * C_, NTHR>>>(x, wl, ws);
    k_stats<<<2, 192>>>(gl, bl, gs, bs);
    k_out<<<(TOT_ / 4 + 255) / 256, 256>>>((float*)d_out);
}

// round 17
// speedup vs baseline: 1.0342x; 1.0342x over previous
#include <cuda_runtime.h>

#define B_   16
#define C_   384
#define H_   56
#define W_   56
#define HW_  3136
#define NHW_ 50176
#define TOT_ 19267584
#define KL   31
#define PL   15
#define KS   5
#define TS   86        // 56 + 2*15
#define STR  90        // even stride, gcd(90,32)=2 -> conflict-free float2 rows
#define WIDE 14        // output columns per thread
#define NTHR 224       // 56 rows x 4 strips -- every lane works
#define TILE_PAD (TS * STR)   // 7740

// Scratch (allocation-free contract: __device__ globals; zero-init at load)
__device__ float g_yl[TOT_];
__device__ float g_ys[TOT_];
__device__ float g_acc[C_ * 4];   // per channel: sumL, sqL, sumS, sqS
__device__ float g_prm[C_ * 3];   // per channel: aL, aS, bias

// Low-register chunked weight pipeline: 2x4-reg double buffer, prefetch 4 taps ahead.
__device__ __forceinline__ void conv_row_c(const float* __restrict__ xr,
                                           const float4* __restrict__ wrow,
                                           float* __restrict__ accL) {
    float xw[16];
    #pragma unroll
    for (int u = 0; u < 8; u++) {
        float2 v = *(const float2*)&xr[2 * u];
        xw[2*u] = v.x; xw[2*u+1] = v.y;
    }

    float wb[8];
    { float4 t4 = wrow[0]; wb[0]=t4.x; wb[1]=t4.y; wb[2]=t4.z; wb[3]=t4.w; }

    #pragma unroll
    for (int jc = 0; jc < 8; jc++) {
        if (jc < 7) {                             // prefetch next 4-weight chunk
            float4 t4 = wrow[jc + 1];
            const int o = ((jc + 1) & 1) * 4;
            wb[o]=t4.x; wb[o+1]=t4.y; wb[o+2]=t4.z; wb[o+3]=t4.w;
        }
        #pragma unroll
        for (int jj = 0; jj < 4; jj++) {
            const int j = jc * 4 + jj;
            if (j >= KL) continue;                // compile-time (only j=31)
            const float wv = wb[(jc & 1) * 4 + jj];
            #pragma unroll
            for (int t = 0; t < WIDE; t++)
                accL[t] = fmaf(xw[(j + t) & 15], wv, accL[t]);
            if ((j & 1) && j <= 27) {             // paired window refill (even addr)
                float2 v = *(const float2*)&xr[j + 15];
                xw[(j + 15) & 15] = v.x;
                xw[(j + 16) & 15] = v.y;
            }
        }
    }
}

__global__ __launch_bounds__(NTHR, 5) void k_conv(const float* __restrict__ x,
                                                  const float* __restrict__ wl_g,
                                                  const float* __restrict__ ws_g) {
    __shared__ __align__(16) float tile[TILE_PAD];
    __shared__ __align__(16) float wlp[KL * 32];   // weight rows padded to 32
    __shared__ float ws[32];
    __shared__ float red[7 * 4];

    const int blk = blockIdx.x;          // n*C + c
    const int c   = blk % C_;
    const int tid = threadIdx.x;
    const float* img = x + (size_t)blk * HW_;

    const int row   = tid % 56;          // output row / interior row
    const int strip = tid / 56;          // 0..3
    const int col0  = strip * WIDE;      // 0, 14, 28, 42 (all even)

    // ---- phase 1: zero HALO ONLY + load weights ----
    // top rows 0..14  = floats [0, 1350); bottom rows 71..85 = [6390, 7740)
    {
        const float4 z4 = make_float4(0.f, 0.f, 0.f, 0.f);
        #pragma unroll
        for (int u = 0; u < 4; u++) {
            int idx = u * NTHR + tid;
            if (idx < 337)       ((float4*)tile)[idx] = z4;                 // [0,1348)
            else if (idx < 674)  *(float4*)&tile[6392 + (idx - 337) * 4] = z4; // [6392,7740)
        }
        if (tid < 4) {
            const int sc[4] = {1348, 1349, 6390, 6391};
            tile[sc[tid]] = 0.f;
        }
        if (tid < 112) {                 // side margins of interior rows 15..70
            int r = 15 + (tid % 56);
            float* rb = &tile[r * STR];
            if (tid < 56) {              // left: cols 0..14
                #pragma unroll
                for (int u = 0; u < 7; u++) *(float2*)&rb[2*u] = make_float2(0.f, 0.f);
                rb[14] = 0.f;
            } else {                     // right: cols 71..89 (incl pad)
                rb[71] = 0.f;
                #pragma unroll
                for (int u = 0; u < 9; u++) *(float2*)&rb[72 + 2*u] = make_float2(0.f, 0.f);
            }
        }
    }
    for (int idx = tid; idx < KL * 32; idx += NTHR) {
        int i = idx >> 5, j = idx & 31;
        wlp[idx] = (j < KL) ? wl_g[c * KL * KL + i * KL + j] : 0.f;
    }
    if (tid < KS * KS) ws[tid] = ws_g[c * KS * KS + tid];
    __syncthreads();

    // ---- phase 2: interior load, exact fit: thread = (row, 14-col strip) ----
    {
        const float* src = img + row * W_ + col0;   // even offset -> 8B aligned
        float* dst = &tile[(row + PL) * STR + PL + col0];
        #pragma unroll
        for (int t = 0; t < WIDE; t += 2) {
            float2 v = *(const float2*)&src[t];
            dst[t]     = v.x;
            dst[t + 1] = v.y;
        }
    }
    __syncthreads();

    const size_t ob = (size_t)blk * HW_ + (size_t)row * W_ + col0;
    float sL = 0.f, qL = 0.f, sS = 0.f, qS = 0.f;

    // ---- 31x31 depthwise conv ----
    {
        float accL[WIDE];
        #pragma unroll
        for (int t = 0; t < WIDE; t++) accL[t] = 0.f;

        #pragma unroll 1
        for (int i = 0; i < KL; i++)
            conv_row_c(&tile[(row + i) * STR + col0],
                       (const float4*)&wlp[i * 32], accL);

        #pragma unroll
        for (int t = 0; t < WIDE; t += 2)
            *(float2*)&g_yl[ob + t] = make_float2(accL[t], accL[t+1]);
        #pragma unroll
        for (int t = 0; t < WIDE; t++) {
            sL += accL[t]; qL = fmaf(accL[t], accL[t], qL);
        }
    }

    // ---- 5x5 depthwise conv (pad 2): even base at col0+12, per-row weights ----
    {
        float accS[WIDE];
        #pragma unroll
        for (int t = 0; t < WIDE; t++) accS[t] = 0.f;
        #pragma unroll 1
        for (int i = 0; i < KS; i++) {
            const float* xr = &tile[(row + i + 13) * STR + col0 + 12];  // even base
            float wsr[KS];
            #pragma unroll
            for (int k = 0; k < KS; k++) wsr[k] = ws[i * KS + k];
            float xv[20];
            #pragma unroll
            for (int u = 0; u < 10; u++) {
                float2 v = *(const float2*)&xr[2 * u];
                xv[2*u] = v.x; xv[2*u+1] = v.y;
            }
            #pragma unroll
            for (int j = 0; j < KS; j++) {
                const float wv = wsr[j];
                #pragma unroll
                for (int t = 0; t < WIDE; t++)
                    accS[t] = fmaf(xv[1 + j + t], wv, accS[t]);
            }
        }

        #pragma unroll
        for (int t = 0; t < WIDE; t += 2)
            *(float2*)&g_ys[ob + t] = make_float2(accS[t], accS[t+1]);
        #pragma unroll
        for (int t = 0; t < WIDE; t++) {
            sS += accS[t]; qS = fmaf(accS[t], accS[t], qS);
        }
    }

    // ---- block reduction of the 4 stats (7 warps) ----
    #pragma unroll
    for (int o = 16; o; o >>= 1) {
        sL += __shfl_down_sync(0xffffffffu, sL, o);
        qL += __shfl_down_sync(0xffffffffu, qL, o);
        sS += __shfl_down_sync(0xffffffffu, sS, o);
        qS += __shfl_down_sync(0xffffffffu, qS, o);
    }
    const int lane = tid & 31, wpid = tid >> 5;
    if (lane == 0) { red[wpid*4+0]=sL; red[wpid*4+1]=qL; red[wpid*4+2]=sS; red[wpid*4+3]=qS; }
    __syncthreads();
    if (tid < 4) {
        float v = 0.f;
        #pragma unroll
        for (int ww = 0; ww < 7; ww++) v += red[ww * 4 + tid];
        atomicAdd(&g_acc[c * 4 + tid], v);
    }
}

// Computes BN affine params, then RE-ZEROES g_acc for the next graph replay
// (device globals start zero-initialized; every replay thus sees zeros).
__global__ void k_stats(const float* __restrict__ gL, const float* __restrict__ bL,
                        const float* __restrict__ gS, const float* __restrict__ bS) {
    int c = blockIdx.x * blockDim.x + threadIdx.x;
    if (c >= C_) return;
    const float inv_n = 1.f / (float)NHW_;
    float mL = g_acc[c*4+0] * inv_n;
    float vL = g_acc[c*4+1] * inv_n - mL * mL;
    float aL = gL[c] * rsqrtf(vL + 1e-5f);
    float mS = g_acc[c*4+2] * inv_n;
    float vS = g_acc[c*4+3] * inv_n - mS * mS;
    float aS = gS[c] * rsqrtf(vS + 1e-5f);
    g_prm[c]        = aL;
    g_prm[C_ + c]   = aS;
    g_prm[2*C_ + c] = bL[c] - mL * aL + bS[c] - mS * aS;
    g_acc[c*4+0] = 0.f; g_acc[c*4+1] = 0.f;
    g_acc[c*4+2] = 0.f; g_acc[c*4+3] = 0.f;
}

__global__ __launch_bounds__(256) void k_out(float* __restrict__ out) {
    int i = blockIdx.x * blockDim.x + threadIdx.x;
    if (i >= TOT_ / 4) return;
    int e = i * 4;
    int c = (e / HW_) % C_;          // HW_ divisible by 4 -> channel constant in float4
    float aL = g_prm[c], aS = g_prm[C_ + c], bb = g_prm[2*C_ + c];
    float4 l = ((const float4*)g_yl)[i];
    float4 s = ((const float4*)g_ys)[i];
    float4 o;
    o.x = fmaf(aL, l.x, fmaf(aS, s.x, bb));
    o.y = fmaf(aL, l.y, fmaf(aS, s.y, bb));
    o.z = fmaf(aL, l.z, fmaf(aS, s.z, bb));
    o.w = fmaf(aL, l.w, fmaf(aS, s.w, bb));
    ((float4*)out)[i] = o;
}

extern "C" void kernel_launch(void* const* d_in, const int* in_sizes, int n_in,
                              void* d_out, int out_size) {
    const float* x  = (const float*)d_in[0];
    const float* wl = (const float*)d_in[1];
    const float* gl = (const float*)d_in[2];
    const float* bl = (const float*)d_in[3];
    const float* ws = (const float*)d_in[4];
    const float* gs = (const float*)d_in[5];
    const float* bs = (const float*)d_in[6];

    k_conv<<<B_ * C_, NTHR>>>(x, wl, ws);
    k_stats<<<2, 192>>>(gl, bl, gs, bs);
    k_out<<<(TOT_ / 4 + 255) / 256, 256>>>((float*)d_out);
}